// round 17
// baseline (speedup 1.0000x reference)
#include <cuda_runtime.h>
#include <math_constants.h>

#define N 512
#define D 128
#define MARGIN 0.3f
#define TS 32
#define KS 130           // padded smem row stride (conflict-free float2)
#define NTILES 136       // triangular 32x32 tiles
#define NBLK (NTILES + N)  // 648: producers then consumers

__device__ float    g_Dm[N * N];
__device__ unsigned g_tflag[NTILES];   // tile-done flags
__device__ double   g_sum  = 0.0;
__device__ int      g_cnt  = 0;
__device__ unsigned g_done = 0u;

__global__ __launch_bounds__(256)
void triplet_fused(const float* __restrict__ X,
                   const int* __restrict__ labels,
                   float* __restrict__ out)
{
    __shared__ union {
        struct { float As[TS * KS]; float Bs[TS * KS]; float nrm[64]; } k1;
        struct { float posA[64]; float wsum[8]; int wcnt[8]; int npos; } k2;
    } sm;

    const int tid  = threadIdx.x;
    const int lane = tid & 31;
    const int warp = tid >> 5;
    const int blk  = blockIdx.x;

    if (blk < NTILES) {
        // ================= PRODUCER: one triangular distance tile ==========
        const int b = blk;
        int ti = (int)((sqrtf(8.0f * (float)b + 1.0f) - 1.0f) * 0.5f);
        while ((ti + 1) * (ti + 2) / 2 <= b) ti++;
        while (ti * (ti + 1) / 2 > b) ti--;
        const int tj = b - ti * (ti + 1) / 2;
        const int i0 = ti * TS, j0 = tj * TS;

        const float2* __restrict__ X2 = (const float2*)X;
        #pragma unroll
        for (int v = 0; v < 8; v++) {
            const int idx = tid + v * 256;
            const int r = idx >> 6, c = idx & 63;
            ((float2*)(sm.k1.As + r * KS))[c] = X2[(i0 + r) * (D / 2) + c];
            ((float2*)(sm.k1.Bs + r * KS))[c] = X2[(j0 + r) * (D / 2) + c];
        }
        __syncthreads();

        #pragma unroll
        for (int r8 = 0; r8 < 8; r8++) {
            const int row = warp * 8 + r8;
            const float* src = (row < 32) ? (sm.k1.As + row * KS)
                                          : (sm.k1.Bs + (row - 32) * KS);
            const float2 v0 = ((const float2*)src)[lane];
            const float2 v1 = ((const float2*)src)[lane + 32];
            float s = v0.x * v0.x + v0.y * v0.y + v1.x * v1.x + v1.y * v1.y;
            #pragma unroll
            for (int o = 16; o > 0; o >>= 1)
                s += __shfl_xor_sync(0xffffffffu, s, o);
            if (lane == 0) sm.k1.nrm[row] = s;
        }
        __syncthreads();

        const int tx = tid & 15, ty = tid >> 4;
        const float* a0p = sm.k1.As + ty * KS;
        const float* a1p = sm.k1.As + (ty + 16) * KS;
        const float* b0p = sm.k1.Bs + tx * KS;
        const float* b1p = sm.k1.Bs + (tx + 16) * KS;

        float c00 = 0.f, c01 = 0.f, c10 = 0.f, c11 = 0.f;
        #pragma unroll 16
        for (int k = 0; k < D; k += 2) {
            const float2 a0 = *(const float2*)(a0p + k);
            const float2 a1 = *(const float2*)(a1p + k);
            const float2 b0 = *(const float2*)(b0p + k);
            const float2 b1 = *(const float2*)(b1p + k);
            c00 += a0.x * b0.x; c00 += a0.y * b0.y;
            c01 += a0.x * b1.x; c01 += a0.y * b1.y;
            c10 += a1.x * b0.x; c10 += a1.y * b0.y;
            c11 += a1.x * b1.x; c11 += a1.y * b1.y;
        }

        const float na0 = sm.k1.nrm[ty],      na1 = sm.k1.nrm[ty + 16];
        const float nb0 = sm.k1.nrm[32 + tx], nb1 = sm.k1.nrm[32 + tx + 16];
        const float d00 = sqrtf(fmaxf(na0 + nb0 - 2.0f * c00, 0.0f));
        const float d01 = sqrtf(fmaxf(na0 + nb1 - 2.0f * c01, 0.0f));
        const float d10 = sqrtf(fmaxf(na1 + nb0 - 2.0f * c10, 0.0f));
        const float d11 = sqrtf(fmaxf(na1 + nb1 - 2.0f * c11, 0.0f));

        const int gi0 = i0 + ty, gi1 = i0 + ty + 16;
        const int gj0 = j0 + tx, gj1 = j0 + tx + 16;
        g_Dm[gi0 * N + gj0] = d00;
        g_Dm[gi0 * N + gj1] = d01;
        g_Dm[gi1 * N + gj0] = d10;
        g_Dm[gi1 * N + gj1] = d11;
        if (ti != tj) {
            g_Dm[gj0 * N + gi0] = d00;
            g_Dm[gj1 * N + gi0] = d01;
            g_Dm[gj0 * N + gi1] = d10;
            g_Dm[gj1 * N + gi1] = d11;
        }

        // release: all threads' stores, then fence, then flag by t0
        __threadfence();
        __syncthreads();
        if (tid == 0) {
            volatile unsigned* vf = g_tflag;
            vf[b] = 1u;
        }
    } else {
        // ================= CONSUMER: one anchor ===========================
        const int i = blk - NTILES;           // anchor 0..511
        const int R = i >> 5;                 // my row-block

        if (tid == 0) sm.k2.npos = 0;
        const int li = __ldg(&labels[i]);

        // Poll my 16 producer tiles: (R,b) for b<=R, (a,R) for a>R. Pure loads.
        if (tid < 16) {
            int a, bb;
            if (tid <= R) { a = R;   bb = tid; }
            else          { a = tid; bb = R;   }
            const int t = a * (a + 1) / 2 + bb;
            volatile unsigned* vf = g_tflag;
            while (vf[t] == 0u) __nanosleep(64);
        }
        __threadfence();
        __syncthreads();

        // R16's proven interior: 2 (dist,label) pairs per thread in registers.
        float dn[2];
        #pragma unroll
        for (int v = 0; v < 2; v++) {
            const int k = tid + v * 256;
            const float dv = __ldcg(&g_Dm[i * N + k]);   // L2-fresh
            const int   lb = __ldg(&labels[k]);
            const bool isPos = (lb == li) && (k != i);
            if (isPos) {
                const int s = atomicAdd(&sm.k2.npos, 1); // smem, ~10/block
                if (s < 64) sm.k2.posA[s] = dv + MARGIN;
            }
            dn[v] = (lb != li) ? dv : CUDART_INF_F;
        }
        __syncthreads();

        int np = sm.k2.npos;
        if (np > 64) np = 64;

        float lsum = 0.0f;
        int   lcnt = 0;
        for (int p = 0; p < np; p++) {
            const float A = sm.k2.posA[p];               // broadcast LDS
            #pragma unroll
            for (int v = 0; v < 2; v++) {
                const float t = A - dn[v];
                if (t > 0.0f)    lsum += t;
                if (t > 1e-16f)  lcnt += 1;
            }
        }

        #pragma unroll
        for (int o = 16; o > 0; o >>= 1) {
            lsum += __shfl_xor_sync(0xffffffffu, lsum, o);
            lcnt += __shfl_xor_sync(0xffffffffu, lcnt, o);
        }
        if (lane == 0) { sm.k2.wsum[warp] = lsum; sm.k2.wcnt[warp] = lcnt; }
        __syncthreads();

        if (tid == 0) {
            float s = 0.0f; int c = 0;
            #pragma unroll
            for (int w = 0; w < 8; w++) { s += sm.k2.wsum[w]; c += sm.k2.wcnt[w]; }
            atomicAdd(&g_sum, (double)s);   // no return -> REDG, pipelined
            atomicAdd(&g_cnt, c);
            __threadfence();
            const unsigned ticket = atomicAdd(&g_done, 1u);
            if (ticket == (unsigned)(N - 1)) {
                // last consumer: all producers finished (every tile was
                // consumed), all consumers contributed.
                const double S = atomicAdd(&g_sum, 0.0);
                const int    C = atomicAdd(&g_cnt, 0);
                out[0] = (float)(S / ((double)C + 1e-16));
                // reset for next graph replay
                g_sum  = 0.0;
                g_cnt  = 0;
                g_done = 0u;
                for (int t = 0; t < NTILES; t++) g_tflag[t] = 0u;
            }
        }
    }
}

extern "C" void kernel_launch(void* const* d_in, const int* in_sizes, int n_in,
                              void* d_out, int out_size) {
    const float* X      = (const float*)d_in[0];   // [512, 128] fp32
    const int*   labels = (const int*)d_in[1];     // [512] int32
    float*       out    = (float*)d_out;           // scalar fp32

    triplet_fused<<<NBLK, 256>>>(X, labels, out);
}